// round 9
// baseline (speedup 1.0000x reference)
#include <cuda_runtime.h>
#include <math.h>
#include <stdint.h>

#define Bq 8
#define Nq 1024
#define Cq 512
#define Hq 4
#define HDq 128
#define SCALEq 0.08838834764831845f

// ---------------- scratch ----------------
__device__ float g_q[Bq * Hq * Nq * HDq];
__device__ float g_k[Bq * Hq * Nq * HDq];
__device__ float g_v[Bq * Hq * Nq * HDq];
__device__ float g_s[(size_t)Bq * Hq * Nq * Nq];
__device__ float g_y[Bq * Nq * Cq];
__device__ float g_x[Bq * Nq * Cq];      // tf32-rounded x
__device__ float g_wq[3 * Cq * Cq];      // tf32-rounded w_qkv
__device__ float g_wp[Cq * Cq];          // tf32-rounded w_proj

// ---------------- tf32 helpers ----------------
__device__ __forceinline__ unsigned f2tf(float f) {
    unsigned r;
    asm("cvt.rna.tf32.f32 %0, %1;" : "=r"(r) : "f"(f));
    return r;
}
__device__ __forceinline__ float tfr(float f) { return __uint_as_float(f2tf(f)); }

__device__ __forceinline__ void mma8(float c[4], const unsigned a[4], const unsigned b[2]) {
    asm volatile(
        "mma.sync.aligned.m16n8k8.row.col.f32.tf32.tf32.f32 "
        "{%0,%1,%2,%3},{%4,%5,%6,%7},{%8,%9},{%0,%1,%2,%3};"
        : "+f"(c[0]), "+f"(c[1]), "+f"(c[2]), "+f"(c[3])
        : "r"(a[0]), "r"(a[1]), "r"(a[2]), "r"(a[3]), "r"(b[0]), "r"(b[1]));
}

// ---------------- cp.async ----------------
__device__ __forceinline__ void cpa16(uint32_t dst, const void* src) {
    asm volatile("cp.async.ca.shared.global [%0], [%1], 16;" :: "r"(dst), "l"(src));
}
#define CP_COMMIT() asm volatile("cp.async.commit_group;")
#define CP_WAIT(n)  asm volatile("cp.async.wait_group %0;" :: "n"(n))

// ---------------- fragment compute, 64x64 warp tile ----------------
// As [row][k] stride 20, Bs [n][k] stride 20
__device__ __forceinline__ void stage_abt64(const float (*As)[20], const float (*Bs)[20],
                                            int wm, int wn, int lr, int lc,
                                            float c[4][8][4]) {
#pragma unroll
    for (int kk = 0; kk < 16; kk += 8) {
        unsigned b[8][2];
#pragma unroll
        for (int u = 0; u < 8; u++) {
            b[u][0] = __float_as_uint(Bs[wn + u * 8 + lr][kk + lc]);
            b[u][1] = __float_as_uint(Bs[wn + u * 8 + lr][kk + lc + 4]);
        }
#pragma unroll
        for (int t = 0; t < 4; t++) {
            unsigned a[4];
            a[0] = __float_as_uint(As[wm + t * 16 + lr][kk + lc]);
            a[1] = __float_as_uint(As[wm + t * 16 + 8 + lr][kk + lc]);
            a[2] = __float_as_uint(As[wm + t * 16 + lr][kk + lc + 4]);
            a[3] = __float_as_uint(As[wm + t * 16 + 8 + lr][kk + lc + 4]);
#pragma unroll
            for (int u = 0; u < 8; u++) mma8(c[t][u], a, b[u]);
        }
    }
}

// As [row][k] stride 20, Bs [k][n] stride 136
__device__ __forceinline__ void stage_pv64(const float (*As)[20], const float (*Bs)[136],
                                           int wm, int wn, int lr, int lc,
                                           float c[4][8][4]) {
#pragma unroll
    for (int kk = 0; kk < 16; kk += 8) {
        unsigned b[8][2];
#pragma unroll
        for (int u = 0; u < 8; u++) {
            b[u][0] = __float_as_uint(Bs[kk + lc][wn + u * 8 + lr]);
            b[u][1] = __float_as_uint(Bs[kk + lc + 4][wn + u * 8 + lr]);
        }
#pragma unroll
        for (int t = 0; t < 4; t++) {
            unsigned a[4];
            a[0] = __float_as_uint(As[wm + t * 16 + lr][kk + lc]);
            a[1] = __float_as_uint(As[wm + t * 16 + 8 + lr][kk + lc]);
            a[2] = __float_as_uint(As[wm + t * 16 + lr][kk + lc + 4]);
            a[3] = __float_as_uint(As[wm + t * 16 + 8 + lr][kk + lc + 4]);
#pragma unroll
            for (int u = 0; u < 8; u++) mma8(c[t][u], a, b[u]);
        }
    }
}

// ===== core: C(128x128) = A(128xK) * B(128xK)^T, 128 thr, 3-stage, 1 sync ====
template <int K>
__device__ __forceinline__ void mma_abt64(const float* __restrict__ A, int lda,
                                          const float* __restrict__ B, int ldb,
                                          float c[4][8][4]) {
    __shared__ __align__(16) float As[3][128][20];
    __shared__ __align__(16) float Bs[3][128][20];
    const int tid = threadIdx.x, lane = tid & 31, wid = tid >> 5;
    const int wm = (wid & 1) * 64, wn = (wid >> 1) * 64;
    const int lr = lane >> 2, lc = lane & 3;
    const int ar = tid >> 2, ac = (tid & 3) * 4;

    auto issue = [&](int s, int k0) {
        uint32_t bA = (uint32_t)__cvta_generic_to_shared(&As[s][0][0]);
        uint32_t bB = (uint32_t)__cvta_generic_to_shared(&Bs[s][0][0]);
#pragma unroll
        for (int i = 0; i < 4; i++) {
            int r = ar + i * 32;
            cpa16(bA + (r * 20 + ac) * 4, A + (size_t)r * lda + k0 + ac);
            cpa16(bB + (r * 20 + ac) * 4, B + (size_t)r * ldb + k0 + ac);
        }
        CP_COMMIT();
    };

    constexpr int NS = K / 16;
    issue(0, 0);
    issue(1, 16);
#pragma unroll 1
    for (int s = 0; s < NS; s++) {
        if (s + 1 < NS) { CP_WAIT(1); } else { CP_WAIT(0); }
        __syncthreads();
        if (s + 2 < NS) issue((s + 2) % 3, (s + 2) * 16);
        stage_abt64(As[s % 3], Bs[s % 3], wm, wn, lr, lc, c);
    }
}

// ===== core: C(128x128) = A(128x1024) * B(1024x128), B row-major [k][128] =====
__device__ __forceinline__ void mma_pv64(const float* __restrict__ A,
                                         const float* __restrict__ B,
                                         float c[4][8][4]) {
    __shared__ __align__(16) float As[3][128][20];
    __shared__ __align__(16) float Bs[3][16][136];
    const int tid = threadIdx.x, lane = tid & 31, wid = tid >> 5;
    const int wm = (wid & 1) * 64, wn = (wid >> 1) * 64;
    const int lr = lane >> 2, lc = lane & 3;
    const int ar = tid >> 2, ac = (tid & 3) * 4;

    auto issue = [&](int s, int k0) {
        uint32_t bA = (uint32_t)__cvta_generic_to_shared(&As[s][0][0]);
        uint32_t bB = (uint32_t)__cvta_generic_to_shared(&Bs[s][0][0]);
#pragma unroll
        for (int i = 0; i < 4; i++) {
            int r = ar + i * 32;
            cpa16(bA + (r * 20 + ac) * 4, A + (size_t)r * 1024 + k0 + ac);
        }
        // B tile: 16 k-rows x 128 d = 512 float4 chunks; 128 thr -> 4 each
#pragma unroll
        for (int i = 0; i < 4; i++) {
            int ch = tid + i * 128;
            int k = ch >> 5, d4 = (ch & 31) * 4;
            cpa16(bB + (k * 136 + d4) * 4, B + (size_t)(k0 + k) * HDq + d4);
        }
        CP_COMMIT();
    };

    constexpr int NS = 1024 / 16;
    issue(0, 0);
    issue(1, 16);
#pragma unroll 1
    for (int s = 0; s < NS; s++) {
        if (s + 1 < NS) { CP_WAIT(1); } else { CP_WAIT(0); }
        __syncthreads();
        if (s + 2 < NS) issue((s + 2) % 3, (s + 2) * 16);
        stage_pv64(As[s % 3], Bs[s % 3], wm, wn, lr, lc, c);
    }
}

// ---------------- kernels ----------------

__global__ void k_round(const float* __restrict__ src, float* __restrict__ dst, int n4) {
    int i = blockIdx.x * blockDim.x + threadIdx.x;
    if (i >= n4) return;
    float4 v = ((const float4*)src)[i];
    v.x = tfr(v.x); v.y = tfr(v.y); v.z = tfr(v.z); v.w = tfr(v.w);
    ((float4*)dst)[i] = v;
}

// qkv = x @ w_qkv^T ; scatter tf32-rounded into g_q/g_k/g_v [B,H,N,HD]
__global__ void __launch_bounds__(128, 3) k_qkv() {
    const int row0 = blockIdx.y * 128;
    const int col0 = blockIdx.x * 128;   // exactly one (part, head) chunk
    float c[4][8][4] = {};
    mma_abt64<Cq>(g_x + (size_t)row0 * Cq, Cq, g_wq + (size_t)col0 * Cq, Cq, c);

    const int part = col0 >> 9;
    const int h = (col0 & 511) >> 7;
    float* dst = (part == 0) ? g_q : (part == 1) ? g_k : g_v;

    const int tid = threadIdx.x, lane = tid & 31, wid = tid >> 5;
    const int wm = (wid & 1) * 64, wn = (wid >> 1) * 64;
    const int lr = lane >> 2, lc = lane & 3;
#pragma unroll
    for (int t = 0; t < 4; t++)
#pragma unroll
        for (int u = 0; u < 8; u++) {
            const int d = wn + u * 8 + 2 * lc;
#pragma unroll
            for (int half = 0; half < 2; half++) {
                const int r = row0 + wm + t * 16 + lr + half * 8;
                const int b = r >> 10, n = r & 1023;
                const size_t base = ((size_t)(b * Hq + h) * Nq + n) * HDq + d;
                dst[base]     = tfr(c[t][u][half * 2 + 0]);
                dst[base + 1] = tfr(c[t][u][half * 2 + 1]);
            }
        }
}

// S[z] = q[z] @ k[z]^T (raw; scale folded into mix)
__global__ void __launch_bounds__(128, 3) k_scores() {
    const int z = blockIdx.z;
    const int row0 = blockIdx.y * 128;
    const int col0 = blockIdx.x * 128;
    float c[4][8][4] = {};
    const float* A = g_q + (size_t)z * Nq * HDq + (size_t)row0 * HDq;
    const float* B = g_k + (size_t)z * Nq * HDq + (size_t)col0 * HDq;
    mma_abt64<HDq>(A, HDq, B, HDq, c);

    float* S = g_s + (size_t)z * Nq * Nq;
    const int tid = threadIdx.x, lane = tid & 31, wid = tid >> 5;
    const int wm = (wid & 1) * 64, wn = (wid >> 1) * 64;
    const int lr = lane >> 2, lc = lane & 3;
#pragma unroll
    for (int t = 0; t < 4; t++)
#pragma unroll
        for (int u = 0; u < 8; u++) {
            const int col = col0 + wn + u * 8 + 2 * lc;
#pragma unroll
            for (int half = 0; half < 2; half++) {
                const int r = row0 + wm + t * 16 + lr + half * 8;
                *(float2*)(S + (size_t)r * Nq + col) =
                    make_float2(c[t][u][half * 2 + 0], c[t][u][half * 2 + 1]);
            }
        }
}

__device__ __forceinline__ float bred(float v, bool is_max, float* red) {
#pragma unroll
    for (int o = 16; o > 0; o >>= 1) {
        float t = __shfl_xor_sync(0xffffffffu, v, o);
        v = is_max ? fmaxf(v, t) : (v + t);
    }
    const int tid = threadIdx.x;
    if ((tid & 31) == 0) red[tid >> 5] = v;
    __syncthreads();
    if (tid == 0) {
        float r = red[0];
        for (int w = 1; w < 8; w++) r = is_max ? fmaxf(r, red[w]) : (r + red[w]);
        red[0] = r;
    }
    __syncthreads();
    float r = red[0];
    __syncthreads();
    return r;
}

// per (b,n): mix heads with M*SCALE, softmax, write probs in place. Pure regs.
__global__ void __launch_bounds__(256) k_mix_softmax(const float* __restrict__ w_main,
                                                     const float* __restrict__ w_rest) {
    __shared__ float red[8];
    const int bn = blockIdx.x;
    const int b = bn >> 10, n = bn & 1023;
    const int tid = threadIdx.x;
    const int m0 = tid * 4;
    const size_t base = ((size_t)(b * Hq) * Nq + n) * Nq;
    const size_t hstride = (size_t)Nq * Nq;

    float4 sh[Hq];
#pragma unroll
    for (int h = 0; h < Hq; h++)
        sh[h] = *(const float4*)(g_s + base + (size_t)h * hstride + m0);

    float Mr[Hq][Hq];
#pragma unroll
    for (int i = 0; i < Hq; i++)
#pragma unroll
        for (int j = 0; j < Hq; j++) {
            float w = (j == i) ? w_main[i] : w_rest[i * (Hq - 1) + j - (j > i ? 1 : 0)];
            Mr[i][j] = w * SCALEq;
        }

#pragma unroll
    for (int i = 0; i < Hq; i++) {
        float v[4];
        v[0] = Mr[i][0] * sh[0].x + Mr[i][1] * sh[1].x + Mr[i][2] * sh[2].x + Mr[i][3] * sh[3].x;
        v[1] = Mr[i][0] * sh[0].y + Mr[i][1] * sh[1].y + Mr[i][2] * sh[2].y + Mr[i][3] * sh[3].y;
        v[2] = Mr[i][0] * sh[0].z + Mr[i][1] * sh[1].z + Mr[i][2] * sh[2].z + Mr[i][3] * sh[3].z;
        v[3] = Mr[i][0] * sh[0].w + Mr[i][1] * sh[1].w + Mr[i][2] * sh[2].w + Mr[i][3] * sh[3].w;
        float lmax = fmaxf(fmaxf(v[0], v[1]), fmaxf(v[2], v[3]));
        const float gmax = bred(lmax, true, red);
        float lsum = 0.f;
#pragma unroll
        for (int t = 0; t < 4; t++) { v[t] = __expf(v[t] - gmax); lsum += v[t]; }
        const float gsum = bred(lsum, false, red);
        const float inv = 1.f / gsum;
        float4 o = make_float4(tfr(v[0] * inv), tfr(v[1] * inv), tfr(v[2] * inv), tfr(v[3] * inv));
        *(float4*)(g_s + base + (size_t)i * hstride + m0) = o;
    }
}

// out[z] = P[z] @ V[z] -> g_y[b, n, h*HD + d] (tf32-rounded for proj)
__global__ void __launch_bounds__(128, 3) k_pv() {
    const int z = blockIdx.z;
    const int row0 = blockIdx.y * 128;  // n
    float c[4][8][4] = {};
    const float* A = g_s + (size_t)z * Nq * Nq + (size_t)row0 * Nq;
    const float* B = g_v + (size_t)z * Nq * HDq;
    mma_pv64(A, B, c);

    const int b = z >> 2, h = z & 3;
    const int tid = threadIdx.x, lane = tid & 31, wid = tid >> 5;
    const int wm = (wid & 1) * 64, wn = (wid >> 1) * 64;
    const int lr = lane >> 2, lc = lane & 3;
#pragma unroll
    for (int t = 0; t < 4; t++)
#pragma unroll
        for (int u = 0; u < 8; u++) {
            const int d = wn + u * 8 + 2 * lc;
#pragma unroll
            for (int half = 0; half < 2; half++) {
                const int n = row0 + wm + t * 16 + lr + half * 8;
                const size_t base = ((size_t)b * Nq + n) * Cq + h * HDq + d;
                g_y[base]     = tfr(c[t][u][half * 2 + 0]);
                g_y[base + 1] = tfr(c[t][u][half * 2 + 1]);
            }
        }
}

// out = y @ w_proj^T + b_proj
__global__ void __launch_bounds__(128, 3)
k_proj(const float* __restrict__ bias, float* __restrict__ out) {
    const int row0 = blockIdx.y * 128;
    const int col0 = blockIdx.x * 128;
    float c[4][8][4] = {};
    mma_abt64<Cq>(g_y + (size_t)row0 * Cq, Cq, g_wp + (size_t)col0 * Cq, Cq, c);

    const int tid = threadIdx.x, lane = tid & 31, wid = tid >> 5;
    const int wm = (wid & 1) * 64, wn = (wid >> 1) * 64;
    const int lr = lane >> 2, lc = lane & 3;
#pragma unroll
    for (int t = 0; t < 4; t++)
#pragma unroll
        for (int u = 0; u < 8; u++) {
            const int col = col0 + wn + u * 8 + 2 * lc;
            const float b0 = bias[col], b1 = bias[col + 1];
#pragma unroll
            for (int half = 0; half < 2; half++) {
                const int r = row0 + wm + t * 16 + lr + half * 8;
                *(float2*)(out + (size_t)r * Cq + col) =
                    make_float2(c[t][u][half * 2 + 0] + b0, c[t][u][half * 2 + 1] + b1);
            }
        }
}

// ---------------- launch ----------------
extern "C" void kernel_launch(void* const* d_in, const int* in_sizes, int n_in,
                              void* d_out, int out_size) {
    const float* x      = (const float*)d_in[0];
    const float* w_qkv  = (const float*)d_in[1];
    const float* w_proj = (const float*)d_in[2];
    const float* b_proj = (const float*)d_in[3];
    const float* w_main = (const float*)d_in[4];
    const float* w_rest = (const float*)d_in[5];
    float* out = (float*)d_out;

    float* p_x;  cudaGetSymbolAddress((void**)&p_x,  g_x);
    float* p_wq; cudaGetSymbolAddress((void**)&p_wq, g_wq);
    float* p_wp; cudaGetSymbolAddress((void**)&p_wp, g_wp);

    dim3 blk(128);
    {
        int n4 = Bq * Nq * Cq / 4;
        k_round<<<(n4 + 255) / 256, 256>>>(x, p_x, n4);
        n4 = 3 * Cq * Cq / 4;
        k_round<<<(n4 + 255) / 256, 256>>>(w_qkv, p_wq, n4);
        n4 = Cq * Cq / 4;
        k_round<<<(n4 + 255) / 256, 256>>>(w_proj, p_wp, n4);
    }
    k_qkv<<<dim3(1536 / 128, (Bq * Nq) / 128), blk>>>();
    k_scores<<<dim3(Nq / 128, Nq / 128, Bq * Hq), blk>>>();
    k_mix_softmax<<<Bq * Nq, dim3(256)>>>(w_main, w_rest);
    k_pv<<<dim3(1, Nq / 128, Bq * Hq), blk>>>();
    k_proj<<<dim3(Cq / 128, (Bq * Nq) / 128), blk>>>(b_proj, out);
}

// round 10
// speedup vs baseline: 1.1935x; 1.1935x over previous
#include <cuda_runtime.h>
#include <math.h>
#include <stdint.h>

#define Bq 8
#define Nq 1024
#define Cq 512
#define Hq 4
#define HDq 128
#define SCALEq 0.08838834764831845f

// ---------------- scratch ----------------
__device__ float g_q[Bq * Hq * Nq * HDq];
__device__ float g_k[Bq * Hq * Nq * HDq];
__device__ float g_v[Bq * Hq * Nq * HDq];
__device__ float g_s[(size_t)Bq * Hq * Nq * Nq];
__device__ float g_y[Bq * Nq * Cq];
__device__ float g_x[Bq * Nq * Cq];      // tf32-rounded x
__device__ float g_wq[3 * Cq * Cq];      // tf32-rounded w_qkv
__device__ float g_wp[Cq * Cq];          // tf32-rounded w_proj

// ---------------- tf32 helpers ----------------
__device__ __forceinline__ unsigned f2tf(float f) {
    unsigned r;
    asm("cvt.rna.tf32.f32 %0, %1;" : "=r"(r) : "f"(f));
    return r;
}
__device__ __forceinline__ float tfr(float f) { return __uint_as_float(f2tf(f)); }

__device__ __forceinline__ void mma8(float c[4], const unsigned a[4], const unsigned b[2]) {
    asm volatile(
        "mma.sync.aligned.m16n8k8.row.col.f32.tf32.tf32.f32 "
        "{%0,%1,%2,%3},{%4,%5,%6,%7},{%8,%9},{%0,%1,%2,%3};"
        : "+f"(c[0]), "+f"(c[1]), "+f"(c[2]), "+f"(c[3])
        : "r"(a[0]), "r"(a[1]), "r"(a[2]), "r"(a[3]), "r"(b[0]), "r"(b[1]));
}

// ---------------- cp.async ----------------
__device__ __forceinline__ void cpa16(uint32_t dst, const void* src) {
    asm volatile("cp.async.ca.shared.global [%0], [%1], 16;" :: "r"(dst), "l"(src));
}
#define CP_COMMIT() asm volatile("cp.async.commit_group;")
#define CP_WAIT(n)  asm volatile("cp.async.wait_group %0;" :: "n"(n))

// ---------------- fragment compute, 64x64 warp tile, BK=32 ----------------
// As [row][k] stride 36, Bs [n][k] stride 36
__device__ __forceinline__ void stage_abt36(const float (*As)[36], const float (*Bs)[36],
                                            int wm, int wn, int lr, int lc,
                                            float c[4][8][4]) {
#pragma unroll
    for (int kk = 0; kk < 32; kk += 8) {
        unsigned b[8][2];
#pragma unroll
        for (int u = 0; u < 8; u++) {
            b[u][0] = __float_as_uint(Bs[wn + u * 8 + lr][kk + lc]);
            b[u][1] = __float_as_uint(Bs[wn + u * 8 + lr][kk + lc + 4]);
        }
#pragma unroll
        for (int t = 0; t < 4; t++) {
            unsigned a[4];
            a[0] = __float_as_uint(As[wm + t * 16 + lr][kk + lc]);
            a[1] = __float_as_uint(As[wm + t * 16 + 8 + lr][kk + lc]);
            a[2] = __float_as_uint(As[wm + t * 16 + lr][kk + lc + 4]);
            a[3] = __float_as_uint(As[wm + t * 16 + 8 + lr][kk + lc + 4]);
#pragma unroll
            for (int u = 0; u < 8; u++) mma8(c[t][u], a, b[u]);
        }
    }
}

// As [row][k] stride 36, Bs [k][n] stride 136
__device__ __forceinline__ void stage_pv36(const float (*As)[36], const float (*Bs)[136],
                                           int wm, int wn, int lr, int lc,
                                           float c[4][8][4]) {
#pragma unroll
    for (int kk = 0; kk < 32; kk += 8) {
        unsigned b[8][2];
#pragma unroll
        for (int u = 0; u < 8; u++) {
            b[u][0] = __float_as_uint(Bs[kk + lc][wn + u * 8 + lr]);
            b[u][1] = __float_as_uint(Bs[kk + lc + 4][wn + u * 8 + lr]);
        }
#pragma unroll
        for (int t = 0; t < 4; t++) {
            unsigned a[4];
            a[0] = __float_as_uint(As[wm + t * 16 + lr][kk + lc]);
            a[1] = __float_as_uint(As[wm + t * 16 + 8 + lr][kk + lc]);
            a[2] = __float_as_uint(As[wm + t * 16 + lr][kk + lc + 4]);
            a[3] = __float_as_uint(As[wm + t * 16 + 8 + lr][kk + lc + 4]);
#pragma unroll
            for (int u = 0; u < 8; u++) mma8(c[t][u], a, b[u]);
        }
    }
}

// ===== core: C(128x128) = A(128xK) * B(128xK)^T, 128 thr, BK=32, 2-stage =====
template <int K>
__device__ __forceinline__ void mma_abt64(const float* __restrict__ A, int lda,
                                          const float* __restrict__ B, int ldb,
                                          float c[4][8][4]) {
    __shared__ __align__(16) float As[2][128][36];
    __shared__ __align__(16) float Bs[2][128][36];
    const int tid = threadIdx.x, lane = tid & 31, wid = tid >> 5;
    const int wm = (wid & 1) * 64, wn = (wid >> 1) * 64;
    const int lr = lane >> 2, lc = lane & 3;

    auto issue = [&](int s, int k0) {
        uint32_t bA = (uint32_t)__cvta_generic_to_shared(&As[s][0][0]);
        uint32_t bB = (uint32_t)__cvta_generic_to_shared(&Bs[s][0][0]);
#pragma unroll
        for (int i = 0; i < 8; i++) {
            int ch = tid + i * 128;            // 0..1023
            int r = ch >> 3, kc = (ch & 7) * 4;
            cpa16(bA + (r * 36 + kc) * 4, A + (size_t)r * lda + k0 + kc);
            cpa16(bB + (r * 36 + kc) * 4, B + (size_t)r * ldb + k0 + kc);
        }
        CP_COMMIT();
    };

    constexpr int NS = K / 32;
    issue(0, 0);
#pragma unroll 1
    for (int s = 0; s < NS; s++) {
        CP_WAIT(0);
        __syncthreads();
        if (s + 1 < NS) issue((s + 1) & 1, (s + 1) * 32);
        stage_abt36(As[s & 1], Bs[s & 1], wm, wn, lr, lc, c);
    }
}

// ===== core: C(128x128) = A(128x1024) * B(1024x128), B row-major [k][128] =====
__device__ __forceinline__ void mma_pv64(const float* __restrict__ A,
                                         const float* __restrict__ B,
                                         float c[4][8][4]) {
    __shared__ __align__(16) float As[2][128][36];
    __shared__ __align__(16) float Bs[2][32][136];
    const int tid = threadIdx.x, lane = tid & 31, wid = tid >> 5;
    const int wm = (wid & 1) * 64, wn = (wid >> 1) * 64;
    const int lr = lane >> 2, lc = lane & 3;

    auto issue = [&](int s, int k0) {
        uint32_t bA = (uint32_t)__cvta_generic_to_shared(&As[s][0][0]);
        uint32_t bB = (uint32_t)__cvta_generic_to_shared(&Bs[s][0][0]);
#pragma unroll
        for (int i = 0; i < 8; i++) {
            int ch = tid + i * 128;            // 0..1023
            int r = ch >> 3, kc = (ch & 7) * 4;
            cpa16(bA + (r * 36 + kc) * 4, A + (size_t)r * 1024 + k0 + kc);
        }
        // B tile: 32 k-rows x 128 d = 1024 float4 chunks / 128 thr = 8 each
#pragma unroll
        for (int i = 0; i < 8; i++) {
            int ch = tid + i * 128;
            int k = ch >> 5, d4 = (ch & 31) * 4;
            cpa16(bB + (k * 136 + d4) * 4, B + (size_t)(k0 + k) * HDq + d4);
        }
        CP_COMMIT();
    };

    constexpr int NS = 1024 / 32;
    issue(0, 0);
#pragma unroll 1
    for (int s = 0; s < NS; s++) {
        CP_WAIT(0);
        __syncthreads();
        if (s + 1 < NS) issue((s + 1) & 1, (s + 1) * 32);
        stage_pv36(As[s & 1], Bs[s & 1], wm, wn, lr, lc, c);
    }
}

// ---------------- kernels ----------------

__global__ void k_round(const float* __restrict__ src, float* __restrict__ dst, int n4) {
    int i = blockIdx.x * blockDim.x + threadIdx.x;
    if (i >= n4) return;
    float4 v = ((const float4*)src)[i];
    v.x = tfr(v.x); v.y = tfr(v.y); v.z = tfr(v.z); v.w = tfr(v.w);
    ((float4*)dst)[i] = v;
}

// qkv = x @ w_qkv^T ; scatter tf32-rounded into g_q/g_k/g_v [B,H,N,HD]
__global__ void __launch_bounds__(128, 2) k_qkv() {
    const int row0 = blockIdx.y * 128;
    const int col0 = blockIdx.x * 128;   // exactly one (part, head) chunk
    float c[4][8][4] = {};
    mma_abt64<Cq>(g_x + (size_t)row0 * Cq, Cq, g_wq + (size_t)col0 * Cq, Cq, c);

    const int part = col0 >> 9;
    const int h = (col0 & 511) >> 7;
    float* dst = (part == 0) ? g_q : (part == 1) ? g_k : g_v;

    const int tid = threadIdx.x, lane = tid & 31, wid = tid >> 5;
    const int wm = (wid & 1) * 64, wn = (wid >> 1) * 64;
    const int lr = lane >> 2, lc = lane & 3;
#pragma unroll
    for (int t = 0; t < 4; t++)
#pragma unroll
        for (int u = 0; u < 8; u++) {
            const int d = wn + u * 8 + 2 * lc;
#pragma unroll
            for (int half = 0; half < 2; half++) {
                const int r = row0 + wm + t * 16 + lr + half * 8;
                const int b = r >> 10, n = r & 1023;
                const size_t base = ((size_t)(b * Hq + h) * Nq + n) * HDq + d;
                dst[base]     = tfr(c[t][u][half * 2 + 0]);
                dst[base + 1] = tfr(c[t][u][half * 2 + 1]);
            }
        }
}

// S[z] = q[z] @ k[z]^T (raw; scale folded into mix)
__global__ void __launch_bounds__(128, 2) k_scores() {
    const int z = blockIdx.z;
    const int row0 = blockIdx.y * 128;
    const int col0 = blockIdx.x * 128;
    float c[4][8][4] = {};
    const float* A = g_q + (size_t)z * Nq * HDq + (size_t)row0 * HDq;
    const float* B = g_k + (size_t)z * Nq * HDq + (size_t)col0 * HDq;
    mma_abt64<HDq>(A, HDq, B, HDq, c);

    float* S = g_s + (size_t)z * Nq * Nq;
    const int tid = threadIdx.x, lane = tid & 31, wid = tid >> 5;
    const int wm = (wid & 1) * 64, wn = (wid >> 1) * 64;
    const int lr = lane >> 2, lc = lane & 3;
#pragma unroll
    for (int t = 0; t < 4; t++)
#pragma unroll
        for (int u = 0; u < 8; u++) {
            const int col = col0 + wn + u * 8 + 2 * lc;
#pragma unroll
            for (int half = 0; half < 2; half++) {
                const int r = row0 + wm + t * 16 + lr + half * 8;
                *(float2*)(S + (size_t)r * Nq + col) =
                    make_float2(c[t][u][half * 2 + 0], c[t][u][half * 2 + 1]);
            }
        }
}

__device__ __forceinline__ float bred(float v, bool is_max, float* red) {
#pragma unroll
    for (int o = 16; o > 0; o >>= 1) {
        float t = __shfl_xor_sync(0xffffffffu, v, o);
        v = is_max ? fmaxf(v, t) : (v + t);
    }
    const int tid = threadIdx.x;
    if ((tid & 31) == 0) red[tid >> 5] = v;
    __syncthreads();
    if (tid == 0) {
        float r = red[0];
        for (int w = 1; w < 8; w++) r = is_max ? fmaxf(r, red[w]) : (r + red[w]);
        red[0] = r;
    }
    __syncthreads();
    float r = red[0];
    __syncthreads();
    return r;
}

// per (b,n): mix heads with M*SCALE, softmax, write probs in place. Pure regs.
__global__ void __launch_bounds__(256) k_mix_softmax(const float* __restrict__ w_main,
                                                     const float* __restrict__ w_rest) {
    __shared__ float red[8];
    const int bn = blockIdx.x;
    const int b = bn >> 10, n = bn & 1023;
    const int tid = threadIdx.x;
    const int m0 = tid * 4;
    const size_t base = ((size_t)(b * Hq) * Nq + n) * Nq;
    const size_t hstride = (size_t)Nq * Nq;

    float4 sh[Hq];
#pragma unroll
    for (int h = 0; h < Hq; h++)
        sh[h] = *(const float4*)(g_s + base + (size_t)h * hstride + m0);

    float Mr[Hq][Hq];
#pragma unroll
    for (int i = 0; i < Hq; i++)
#pragma unroll
        for (int j = 0; j < Hq; j++) {
            float w = (j == i) ? w_main[i] : w_rest[i * (Hq - 1) + j - (j > i ? 1 : 0)];
            Mr[i][j] = w * SCALEq;
        }

#pragma unroll
    for (int i = 0; i < Hq; i++) {
        float v[4];
        v[0] = Mr[i][0] * sh[0].x + Mr[i][1] * sh[1].x + Mr[i][2] * sh[2].x + Mr[i][3] * sh[3].x;
        v[1] = Mr[i][0] * sh[0].y + Mr[i][1] * sh[1].y + Mr[i][2] * sh[2].y + Mr[i][3] * sh[3].y;
        v[2] = Mr[i][0] * sh[0].z + Mr[i][1] * sh[1].z + Mr[i][2] * sh[2].z + Mr[i][3] * sh[3].z;
        v[3] = Mr[i][0] * sh[0].w + Mr[i][1] * sh[1].w + Mr[i][2] * sh[2].w + Mr[i][3] * sh[3].w;
        float lmax = fmaxf(fmaxf(v[0], v[1]), fmaxf(v[2], v[3]));
        const float gmax = bred(lmax, true, red);
        float lsum = 0.f;
#pragma unroll
        for (int t = 0; t < 4; t++) { v[t] = __expf(v[t] - gmax); lsum += v[t]; }
        const float gsum = bred(lsum, false, red);
        const float inv = 1.f / gsum;
        float4 o = make_float4(tfr(v[0] * inv), tfr(v[1] * inv), tfr(v[2] * inv), tfr(v[3] * inv));
        *(float4*)(g_s + base + (size_t)i * hstride + m0) = o;
    }
}

// out[z] = P[z] @ V[z] -> g_y[b, n, h*HD + d] (tf32-rounded for proj)
__global__ void __launch_bounds__(128, 2) k_pv() {
    const int z = blockIdx.z;
    const int row0 = blockIdx.y * 128;  // n
    float c[4][8][4] = {};
    const float* A = g_s + (size_t)z * Nq * Nq + (size_t)row0 * Nq;
    const float* B = g_v + (size_t)z * Nq * HDq;
    mma_pv64(A, B, c);

    const int b = z >> 2, h = z & 3;
    const int tid = threadIdx.x, lane = tid & 31, wid = tid >> 5;
    const int wm = (wid & 1) * 64, wn = (wid >> 1) * 64;
    const int lr = lane >> 2, lc = lane & 3;
#pragma unroll
    for (int t = 0; t < 4; t++)
#pragma unroll
        for (int u = 0; u < 8; u++) {
            const int d = wn + u * 8 + 2 * lc;
#pragma unroll
            for (int half = 0; half < 2; half++) {
                const int n = row0 + wm + t * 16 + lr + half * 8;
                const size_t base = ((size_t)b * Nq + n) * Cq + h * HDq + d;
                g_y[base]     = tfr(c[t][u][half * 2 + 0]);
                g_y[base + 1] = tfr(c[t][u][half * 2 + 1]);
            }
        }
}

// out = y @ w_proj^T + b_proj
__global__ void __launch_bounds__(128, 2)
k_proj(const float* __restrict__ bias, float* __restrict__ out) {
    const int row0 = blockIdx.y * 128;
    const int col0 = blockIdx.x * 128;
    float c[4][8][4] = {};
    mma_abt64<Cq>(g_y + (size_t)row0 * Cq, Cq, g_wp + (size_t)col0 * Cq, Cq, c);

    const int tid = threadIdx.x, lane = tid & 31, wid = tid >> 5;
    const int wm = (wid & 1) * 64, wn = (wid >> 1) * 64;
    const int lr = lane >> 2, lc = lane & 3;
#pragma unroll
    for (int t = 0; t < 4; t++)
#pragma unroll
        for (int u = 0; u < 8; u++) {
            const int col = col0 + wn + u * 8 + 2 * lc;
            const float b0 = bias[col], b1 = bias[col + 1];
#pragma unroll
            for (int half = 0; half < 2; half++) {
                const int r = row0 + wm + t * 16 + lr + half * 8;
                *(float2*)(out + (size_t)r * Cq + col) =
                    make_float2(c[t][u][half * 2 + 0] + b0, c[t][u][half * 2 + 1] + b1);
            }
        }
}

// ---------------- launch ----------------
extern "C" void kernel_launch(void* const* d_in, const int* in_sizes, int n_in,
                              void* d_out, int out_size) {
    const float* x      = (const float*)d_in[0];
    const float* w_qkv  = (const float*)d_in[1];
    const float* w_proj = (const float*)d_in[2];
    const float* b_proj = (const float*)d_in[3];
    const float* w_main = (const float*)d_in[4];
    const float* w_rest = (const float*)d_in[5];
    float* out = (float*)d_out;

    float* p_x;  cudaGetSymbolAddress((void**)&p_x,  g_x);
    float* p_wq; cudaGetSymbolAddress((void**)&p_wq, g_wq);
    float* p_wp; cudaGetSymbolAddress((void**)&p_wp, g_wp);

    dim3 blk(128);
    {
        int n4 = Bq * Nq * Cq / 4;
        k_round<<<(n4 + 255) / 256, 256>>>(x, p_x, n4);
        n4 = 3 * Cq * Cq / 4;
        k_round<<<(n4 + 255) / 256, 256>>>(w_qkv, p_wq, n4);
        n4 = Cq * Cq / 4;
        k_round<<<(n4 + 255) / 256, 256>>>(w_proj, p_wp, n4);
    }
    k_qkv<<<dim3(1536 / 128, (Bq * Nq) / 128), blk>>>();
    k_scores<<<dim3(Nq / 128, Nq / 128, Bq * Hq), blk>>>();
    k_mix_softmax<<<Bq * Nq, dim3(256)>>>(w_main, w_rest);
    k_pv<<<dim3(1, Nq / 128, Bq * Hq), blk>>>();
    k_proj<<<dim3(Cq / 128, (Bq * Nq) / 128), blk>>>(b_proj, out);
}

// round 12
// speedup vs baseline: 1.8281x; 1.5317x over previous
#include <cuda_runtime.h>
#include <cuda_fp16.h>
#include <math.h>
#include <stdint.h>

#define Bq 8
#define Nq 1024
#define Cq 512
#define Hq 4
#define HDq 128
#define SCALEq 0.08838834764831845f

// ---------------- scratch ----------------
__device__ __half g_q[Bq * Hq * Nq * HDq];
__device__ __half g_k[Bq * Hq * Nq * HDq];
__device__ __half g_v[Bq * Hq * Nq * HDq];
__device__ float  g_s[(size_t)Bq * Hq * Nq * Nq];   // raw scores f32
__device__ __half g_p[(size_t)Bq * Hq * Nq * Nq];   // probs fp16
__device__ __half g_y[Bq * Nq * Cq];
__device__ __half g_x[Bq * Nq * Cq];
__device__ __half g_wq[3 * Cq * Cq];
__device__ __half g_wp[Cq * Cq];

// ---------------- helpers ----------------
__device__ __forceinline__ uint32_t smem_u32(const void* p) {
    uint32_t a;
    asm("{ .reg .u64 t; cvta.to.shared.u64 t, %1; cvt.u32.u64 %0, t; }" : "=r"(a) : "l"(p));
    return a;
}
__device__ __forceinline__ void cpa16(uint32_t dst, const void* src) {
    asm volatile("cp.async.ca.shared.global [%0], [%1], 16;" :: "r"(dst), "l"(src));
}
#define CP_COMMIT() asm volatile("cp.async.commit_group;")
#define CP_WAIT(n)  asm volatile("cp.async.wait_group %0;" :: "n"(n))

__device__ __forceinline__ void ldsm4(uint32_t& r0, uint32_t& r1, uint32_t& r2, uint32_t& r3,
                                      uint32_t addr) {
    asm volatile("ldmatrix.sync.aligned.m8n8.x4.shared.b16 {%0,%1,%2,%3}, [%4];"
                 : "=r"(r0), "=r"(r1), "=r"(r2), "=r"(r3) : "r"(addr));
}
__device__ __forceinline__ void ldsm4t(uint32_t& r0, uint32_t& r1, uint32_t& r2, uint32_t& r3,
                                       uint32_t addr) {
    asm volatile("ldmatrix.sync.aligned.m8n8.x4.trans.shared.b16 {%0,%1,%2,%3}, [%4];"
                 : "=r"(r0), "=r"(r1), "=r"(r2), "=r"(r3) : "r"(addr));
}
__device__ __forceinline__ void mma16(float c[4], const uint32_t a[4], uint32_t b0, uint32_t b1) {
    asm volatile(
        "mma.sync.aligned.m16n8k16.row.col.f32.f16.f16.f32 "
        "{%0,%1,%2,%3},{%4,%5,%6,%7},{%8,%9},{%0,%1,%2,%3};"
        : "+f"(c[0]), "+f"(c[1]), "+f"(c[2]), "+f"(c[3])
        : "r"(a[0]), "r"(a[1]), "r"(a[2]), "r"(a[3]), "r"(b0), "r"(b1));
}

// A smem: 128 rows x 40 halfs (80 B row); B abt smem: same. B pv smem: 32 x 136 halfs (272 B).
#define RSA 80
#define RSBT 272
#define ABUF 10240   // 128*80
#define BTBUF 8704   // 32*272

// ===== core: C(128x128) = A(128xK) * B(128xK)^T, fp16 K-major, 128 thr, BK=32 =====
template <int K>
__device__ __forceinline__ void hgemm_abt(const __half* __restrict__ A, int lda,
                                          const __half* __restrict__ B, int ldb,
                                          float c[4][8][4]) {
    __shared__ __align__(16) char sA[2 * ABUF];
    __shared__ __align__(16) char sB[2 * ABUF];
    const int tid = threadIdx.x, lane = tid & 31, wid = tid >> 5;
    const int wm = (wid & 1) * 64, wn = (wid >> 1) * 64;
    const uint32_t sbA = smem_u32(sA), sbB = smem_u32(sB);
    // ldmatrix base addrs (lane-dependent)
    const uint32_t aBase = sbA + (uint32_t)((wm + (lane & 7) + ((lane >> 3) & 1) * 8) * RSA
                                            + (lane >> 4) * 16);
    const uint32_t bBase = sbB + (uint32_t)((wn + (lane & 7) + (lane >> 4) * 8) * RSA
                                            + ((lane >> 3) & 1) * 16);

    auto issue = [&](int buf, int k0) {
        const uint32_t bA = sbA + buf * ABUF;
        const uint32_t bB = sbB + buf * ABUF;
#pragma unroll
        for (int i = 0; i < 4; i++) {
            int ch = tid + i * 128;            // 0..511
            int r = ch >> 2, c16 = (ch & 3) * 16;
            cpa16(bA + r * RSA + c16, (const char*)(A + (size_t)r * lda + k0) + c16);
            cpa16(bB + r * RSA + c16, (const char*)(B + (size_t)r * ldb + k0) + c16);
        }
        CP_COMMIT();
    };

    constexpr int NS = K / 32;
    issue(0, 0);
#pragma unroll 1
    for (int s = 0; s < NS; s++) {
        CP_WAIT(0);
        __syncthreads();
        if (s + 1 < NS) issue((s + 1) & 1, (s + 1) * 32);
        const uint32_t off = (s & 1) * ABUF;
#pragma unroll
        for (int kk = 0; kk < 2; kk++) {       // k16 steps
            uint32_t a[4][4], b[4][4];
#pragma unroll
            for (int t = 0; t < 4; t++)
                ldsm4(a[t][0], a[t][1], a[t][2], a[t][3], aBase + off + t * 1280 + kk * 32);
#pragma unroll
            for (int du = 0; du < 4; du++)
                ldsm4(b[du][0], b[du][1], b[du][2], b[du][3], bBase + off + du * 1280 + kk * 32);
#pragma unroll
            for (int t = 0; t < 4; t++)
#pragma unroll
                for (int du = 0; du < 4; du++) {
                    mma16(c[t][du * 2 + 0], a[t], b[du][0], b[du][1]);
                    mma16(c[t][du * 2 + 1], a[t], b[du][2], b[du][3]);
                }
        }
    }
}

// ===== core: C(128x128) = P(128x1024) * V(1024x128), V row-major [m][d] ==========
__device__ __forceinline__ void hgemm_pv(const __half* __restrict__ A,
                                         const __half* __restrict__ V,
                                         float c[4][8][4]) {
    __shared__ __align__(16) char sA[2 * ABUF];
    __shared__ __align__(16) char sB[2 * BTBUF];
    const int tid = threadIdx.x, lane = tid & 31, wid = tid >> 5;
    const int wm = (wid & 1) * 64, wn = (wid >> 1) * 64;
    const uint32_t sbA = smem_u32(sA), sbB = smem_u32(sB);
    const uint32_t aBase = sbA + (uint32_t)((wm + (lane & 7) + ((lane >> 3) & 1) * 8) * RSA
                                            + (lane >> 4) * 16);
    const uint32_t btBase = sbB + (uint32_t)(((lane & 7) + ((lane >> 3) & 1) * 8) * RSBT
                                             + (wn + (lane >> 4) * 8) * 2);

    auto issue = [&](int buf, int k0) {
        const uint32_t bA = sbA + buf * ABUF;
        const uint32_t bB = sbB + buf * BTBUF;
#pragma unroll
        for (int i = 0; i < 4; i++) {
            int ch = tid + i * 128;            // A: 0..511
            int r = ch >> 2, c16 = (ch & 3) * 16;
            cpa16(bA + r * RSA + c16, (const char*)(A + (size_t)r * 1024 + k0) + c16);
        }
#pragma unroll
        for (int i = 0; i < 4; i++) {          // B: 32 rows x 256 B = 512 chunks
            int ch = tid + i * 128;
            int r = ch >> 4, c16 = (ch & 15) * 16;
            cpa16(bB + r * RSBT + c16, (const char*)(V + (size_t)(k0 + r) * HDq) + c16);
        }
        CP_COMMIT();
    };

    constexpr int NS = 1024 / 32;
    issue(0, 0);
#pragma unroll 1
    for (int s = 0; s < NS; s++) {
        CP_WAIT(0);
        __syncthreads();
        if (s + 1 < NS) issue((s + 1) & 1, (s + 1) * 32);
        const uint32_t offA = (s & 1) * ABUF;
        const uint32_t offB = (s & 1) * BTBUF;
#pragma unroll
        for (int kk = 0; kk < 2; kk++) {
            uint32_t a[4][4], b[4][4];
#pragma unroll
            for (int t = 0; t < 4; t++)
                ldsm4(a[t][0], a[t][1], a[t][2], a[t][3], aBase + offA + t * 1280 + kk * 32);
#pragma unroll
            for (int du = 0; du < 4; du++)
                ldsm4t(b[du][0], b[du][1], b[du][2], b[du][3],
                       btBase + offB + kk * (16 * RSBT) + du * 32);
#pragma unroll
            for (int t = 0; t < 4; t++)
#pragma unroll
                for (int du = 0; du < 4; du++) {
                    mma16(c[t][du * 2 + 0], a[t], b[du][0], b[du][1]);
                    mma16(c[t][du * 2 + 1], a[t], b[du][2], b[du][3]);
                }
        }
    }
}

// ---------------- kernels ----------------

__global__ void k_round16(const float* __restrict__ src, __half* __restrict__ dst, int n4) {
    int i = blockIdx.x * blockDim.x + threadIdx.x;
    if (i >= n4) return;
    float4 v = ((const float4*)src)[i];
    ((__half2*)dst)[2 * i]     = __floats2half2_rn(v.x, v.y);
    ((__half2*)dst)[2 * i + 1] = __floats2half2_rn(v.z, v.w);
}

// qkv = x @ w_qkv^T ; scatter fp16 into g_q/g_k/g_v [b,h,n,d]
__global__ void __launch_bounds__(128, 2) k_qkv() {
    const int row0 = blockIdx.y * 128;
    const int col0 = blockIdx.x * 128;
    float c[4][8][4] = {};
    hgemm_abt<Cq>(g_x + (size_t)row0 * Cq, Cq, g_wq + (size_t)col0 * Cq, Cq, c);

    const int part = col0 >> 9;
    const int h = (col0 & 511) >> 7;
    __half* dst = (part == 0) ? g_q : (part == 1) ? g_k : g_v;

    const int tid = threadIdx.x, lane = tid & 31, wid = tid >> 5;
    const int wm = (wid & 1) * 64, wn = (wid >> 1) * 64;
    const int lr = lane >> 2, lc = lane & 3;
#pragma unroll
    for (int t = 0; t < 4; t++)
#pragma unroll
        for (int u = 0; u < 8; u++) {
            const int d = wn + u * 8 + 2 * lc;
#pragma unroll
            for (int half = 0; half < 2; half++) {
                const int r = row0 + wm + t * 16 + lr + half * 8;
                const int b = r >> 10, n = r & 1023;
                __half* p = dst + ((size_t)((b * Hq + h) * Nq + n)) * HDq + d;
                *(__half2*)p = __floats2half2_rn(c[t][u][half * 2 + 0], c[t][u][half * 2 + 1]);
            }
        }
}

// S[z] = q[z] @ k[z]^T (raw f32; scale folded into mix)
__global__ void __launch_bounds__(128, 2) k_scores() {
    const int z = blockIdx.z;
    const int row0 = blockIdx.y * 128;
    const int col0 = blockIdx.x * 128;
    float c[4][8][4] = {};
    const __half* A = g_q + (size_t)z * Nq * HDq + (size_t)row0 * HDq;
    const __half* B = g_k + (size_t)z * Nq * HDq + (size_t)col0 * HDq;
    hgemm_abt<HDq>(A, HDq, B, HDq, c);

    float* S = g_s + (size_t)z * Nq * Nq;
    const int tid = threadIdx.x, lane = tid & 31, wid = tid >> 5;
    const int wm = (wid & 1) * 64, wn = (wid >> 1) * 64;
    const int lr = lane >> 2, lc = lane & 3;
#pragma unroll
    for (int t = 0; t < 4; t++)
#pragma unroll
        for (int u = 0; u < 8; u++) {
            const int col = col0 + wn + u * 8 + 2 * lc;
#pragma unroll
            for (int half = 0; half < 2; half++) {
                const int r = row0 + wm + t * 16 + lr + half * 8;
                *(float2*)(S + (size_t)r * Nq + col) =
                    make_float2(c[t][u][half * 2 + 0], c[t][u][half * 2 + 1]);
            }
        }
}

__device__ __forceinline__ float bred(float v, bool is_max, float* red) {
#pragma unroll
    for (int o = 16; o > 0; o >>= 1) {
        float t = __shfl_xor_sync(0xffffffffu, v, o);
        v = is_max ? fmaxf(v, t) : (v + t);
    }
    const int tid = threadIdx.x;
    if ((tid & 31) == 0) red[tid >> 5] = v;
    __syncthreads();
    if (tid == 0) {
        float r = red[0];
        for (int w = 1; w < 8; w++) r = is_max ? fmaxf(r, red[w]) : (r + red[w]);
        red[0] = r;
    }
    __syncthreads();
    float r = red[0];
    __syncthreads();
    return r;
}

// per (b,n): mix heads with M*SCALE, softmax; read f32 scores, write fp16 probs
__global__ void __launch_bounds__(256) k_mix_softmax(const float* __restrict__ w_main,
                                                     const float* __restrict__ w_rest) {
    __shared__ float red[8];
    const int bn = blockIdx.x;
    const int b = bn >> 10, n = bn & 1023;
    const int tid = threadIdx.x;
    const int m0 = tid * 4;
    const size_t base = ((size_t)(b * Hq) * Nq + n) * Nq;
    const size_t hstride = (size_t)Nq * Nq;

    float4 sh[Hq];
#pragma unroll
    for (int h = 0; h < Hq; h++)
        sh[h] = *(const float4*)(g_s + base + (size_t)h * hstride + m0);

    float Mr[Hq][Hq];
#pragma unroll
    for (int i = 0; i < Hq; i++)
#pragma unroll
        for (int j = 0; j < Hq; j++) {
            float w = (j == i) ? w_main[i] : w_rest[i * (Hq - 1) + j - (j > i ? 1 : 0)];
            Mr[i][j] = w * SCALEq;
        }

#pragma unroll
    for (int i = 0; i < Hq; i++) {
        float v[4];
        v[0] = Mr[i][0] * sh[0].x + Mr[i][1] * sh[1].x + Mr[i][2] * sh[2].x + Mr[i][3] * sh[3].x;
        v[1] = Mr[i][0] * sh[0].y + Mr[i][1] * sh[1].y + Mr[i][2] * sh[2].y + Mr[i][3] * sh[3].y;
        v[2] = Mr[i][0] * sh[0].z + Mr[i][1] * sh[1].z + Mr[i][2] * sh[2].z + Mr[i][3] * sh[3].z;
        v[3] = Mr[i][0] * sh[0].w + Mr[i][1] * sh[1].w + Mr[i][2] * sh[2].w + Mr[i][3] * sh[3].w;
        float lmax = fmaxf(fmaxf(v[0], v[1]), fmaxf(v[2], v[3]));
        const float gmax = bred(lmax, true, red);
        float lsum = 0.f;
#pragma unroll
        for (int t = 0; t < 4; t++) { v[t] = __expf(v[t] - gmax); lsum += v[t]; }
        const float gsum = bred(lsum, false, red);
        const float inv = 1.f / gsum;
        __half* p = g_p + base + (size_t)i * hstride + m0;
        *(__half2*)(p)     = __floats2half2_rn(v[0] * inv, v[1] * inv);
        *(__half2*)(p + 2) = __floats2half2_rn(v[2] * inv, v[3] * inv);
    }
}

// out[z] = P[z] @ V[z] -> g_y[b, n, h*HD + d] fp16
__global__ void __launch_bounds__(128, 2) k_pv() {
    const int z = blockIdx.z;
    const int row0 = blockIdx.y * 128;   // n
    float c[4][8][4] = {};
    const __half* A = g_p + (size_t)z * Nq * Nq + (size_t)row0 * Nq;
    const __half* V = g_v + (size_t)z * Nq * HDq;
    hgemm_pv(A, V, c);

    const int b = z >> 2, h = z & 3;
    const int tid = threadIdx.x, lane = tid & 31, wid = tid >> 5;
    const int wm = (wid & 1) * 64, wn = (wid >> 1) * 64;
    const int lr = lane >> 2, lc = lane & 3;
#pragma unroll
    for (int t = 0; t < 4; t++)
#pragma unroll
        for (int u = 0; u < 8; u++) {
            const int d = wn + u * 8 + 2 * lc;
#pragma unroll
            for (int half = 0; half < 2; half++) {
                const int n = row0 + wm + t * 16 + lr + half * 8;
                __half* p = g_y + ((size_t)b * Nq + n) * Cq + h * HDq + d;
                *(__half2*)p = __floats2half2_rn(c[t][u][half * 2 + 0], c[t][u][half * 2 + 1]);
            }
        }
}

// out = y @ w_proj^T + b_proj (f32 out)
__global__ void __launch_bounds__(128, 2)
k_proj(const float* __restrict__ bias, float* __restrict__ out) {
    const int row0 = blockIdx.y * 128;
    const int col0 = blockIdx.x * 128;
    float c[4][8][4] = {};
    hgemm_abt<Cq>(g_y + (size_t)row0 * Cq, Cq, g_wp + (size_t)col0 * Cq, Cq, c);

    const int tid = threadIdx.x, lane = tid & 31, wid = tid >> 5;
    const int wm = (wid & 1) * 64, wn = (wid >> 1) * 64;
    const int lr = lane >> 2, lc = lane & 3;
#pragma unroll
    for (int t = 0; t < 4; t++)
#pragma unroll
        for (int u = 0; u < 8; u++) {
            const int col = col0 + wn + u * 8 + 2 * lc;
            const float b0 = bias[col], b1 = bias[col + 1];
#pragma unroll
            for (int half = 0; half < 2; half++) {
                const int r = row0 + wm + t * 16 + lr + half * 8;
                *(float2*)(out + (size_t)r * Cq + col) =
                    make_float2(c[t][u][half * 2 + 0] + b0, c[t][u][half * 2 + 1] + b1);
            }
        }
}

// ---------------- launch ----------------
extern "C" void kernel_launch(void* const* d_in, const int* in_sizes, int n_in,
                              void* d_out, int out_size) {
    const float* x      = (const float*)d_in[0];
    const float* w_qkv  = (const float*)d_in[1];
    const float* w_proj = (const float*)d_in[2];
    const float* b_proj = (const float*)d_in[3];
    const float* w_main = (const float*)d_in[4];
    const float* w_rest = (const float*)d_in[5];
    float* out = (float*)d_out;

    __half* p_x;  cudaGetSymbolAddress((void**)&p_x,  g_x);
    __half* p_wq; cudaGetSymbolAddress((void**)&p_wq, g_wq);
    __half* p_wp; cudaGetSymbolAddress((void**)&p_wp, g_wp);

    {
        int n4 = Bq * Nq * Cq / 4;
        k_round16<<<(n4 + 255) / 256, 256>>>(x, p_x, n4);
        n4 = 3 * Cq * Cq / 4;
        k_round16<<<(n4 + 255) / 256, 256>>>(w_qkv, p_wq, n4);
        n4 = Cq * Cq / 4;
        k_round16<<<(n4 + 255) / 256, 256>>>(w_proj, p_wp, n4);
    }
    k_qkv<<<dim3(1536 / 128, (Bq * Nq) / 128), 128>>>();
    k_scores<<<dim3(Nq / 128, Nq / 128, Bq * Hq), 128>>>();
    k_mix_softmax<<<Bq * Nq, 256>>>(w_main, w_rest);
    k_pv<<<dim3(1, Nq / 128, Bq * Hq), 128>>>();
    k_proj<<<dim3(Cq / 128, (Bq * Nq) / 128), 128>>>(b_proj, out);
}

// round 13
// speedup vs baseline: 1.9108x; 1.0452x over previous
#include <cuda_runtime.h>
#include <cuda_fp16.h>
#include <math.h>
#include <stdint.h>

#define Bq 8
#define Nq 1024
#define Cq 512
#define Hq 4
#define HDq 128
#define SCALEq 0.08838834764831845f

// ---------------- scratch ----------------
__device__ __half g_q[Bq * Hq * Nq * HDq];
__device__ __half g_k[Bq * Hq * Nq * HDq];
__device__ __half g_v[Bq * Hq * Nq * HDq];
__device__ float  g_s[(size_t)Bq * Hq * Nq * Nq];   // raw scores f32
__device__ __half g_p[(size_t)Bq * Hq * Nq * Nq];   // probs fp16
__device__ __half g_y[Bq * Nq * Cq];
__device__ __half g_x[Bq * Nq * Cq];
__device__ __half g_wq[3 * Cq * Cq];
__device__ __half g_wp[Cq * Cq];

// ---------------- helpers ----------------
__device__ __forceinline__ uint32_t smem_u32(const void* p) {
    uint32_t a;
    asm("{ .reg .u64 t; cvta.to.shared.u64 t, %1; cvt.u32.u64 %0, t; }" : "=r"(a) : "l"(p));
    return a;
}
__device__ __forceinline__ void cpa16(uint32_t dst, const void* src) {
    asm volatile("cp.async.ca.shared.global [%0], [%1], 16;" :: "r"(dst), "l"(src));
}
#define CP_COMMIT() asm volatile("cp.async.commit_group;")
#define CP_WAIT(n)  asm volatile("cp.async.wait_group %0;" :: "n"(n))

__device__ __forceinline__ void ldsm4(uint32_t& r0, uint32_t& r1, uint32_t& r2, uint32_t& r3,
                                      uint32_t addr) {
    asm volatile("ldmatrix.sync.aligned.m8n8.x4.shared.b16 {%0,%1,%2,%3}, [%4];"
                 : "=r"(r0), "=r"(r1), "=r"(r2), "=r"(r3) : "r"(addr));
}
__device__ __forceinline__ void ldsm4t(uint32_t& r0, uint32_t& r1, uint32_t& r2, uint32_t& r3,
                                       uint32_t addr) {
    asm volatile("ldmatrix.sync.aligned.m8n8.x4.trans.shared.b16 {%0,%1,%2,%3}, [%4];"
                 : "=r"(r0), "=r"(r1), "=r"(r2), "=r"(r3) : "r"(addr));
}
__device__ __forceinline__ void mma16(float c[4], const uint32_t a[4], uint32_t b0, uint32_t b1) {
    asm volatile(
        "mma.sync.aligned.m16n8k16.row.col.f32.f16.f16.f32 "
        "{%0,%1,%2,%3},{%4,%5,%6,%7},{%8,%9},{%0,%1,%2,%3};"
        : "+f"(c[0]), "+f"(c[1]), "+f"(c[2]), "+f"(c[3])
        : "r"(a[0]), "r"(a[1]), "r"(a[2]), "r"(a[3]), "r"(b0), "r"(b1));
}

// BK=64. A/B abt smem row: 64 halfs + 8 pad = 144 B. PV B row: 128 halfs + 8 pad = 272 B.
#define RSA 144
#define RSBT 272
#define ABUF 18432   // 128*144
#define BTBUF 17408  // 64*272

// ===== core: C(128x128) = A(128xK) * B(128xK)^T, fp16 K-major, 128 thr, BK=64 =====
template <int K>
__device__ __forceinline__ void hgemm_abt(const __half* __restrict__ A, int lda,
                                          const __half* __restrict__ B, int ldb,
                                          float c[4][8][4]) {
    extern __shared__ __align__(16) char smem_dyn[];
    char* sA = smem_dyn;
    char* sB = smem_dyn + 2 * ABUF;
    const int tid = threadIdx.x, lane = tid & 31, wid = tid >> 5;
    const int wm = (wid & 1) * 64, wn = (wid >> 1) * 64;
    const uint32_t sbA = smem_u32(sA), sbB = smem_u32(sB);
    const uint32_t aBase = sbA + (uint32_t)((wm + (lane & 7) + ((lane >> 3) & 1) * 8) * RSA
                                            + (lane >> 4) * 16);
    const uint32_t bBase = sbB + (uint32_t)((wn + (lane & 7) + (lane >> 4) * 8) * RSA
                                            + ((lane >> 3) & 1) * 16);

    auto issue = [&](int buf, int k0) {
        const uint32_t bA = sbA + buf * ABUF;
        const uint32_t bB = sbB + buf * ABUF;
#pragma unroll
        for (int i = 0; i < 8; i++) {
            int ch = tid + i * 128;            // 0..1023 (128 rows x 8 chunks)
            int r = ch >> 3, c16 = (ch & 7) * 16;
            cpa16(bA + r * RSA + c16, (const char*)(A + (size_t)r * lda + k0) + c16);
            cpa16(bB + r * RSA + c16, (const char*)(B + (size_t)r * ldb + k0) + c16);
        }
        CP_COMMIT();
    };

    constexpr int NS = K / 64;
    issue(0, 0);
#pragma unroll 1
    for (int s = 0; s < NS; s++) {
        CP_WAIT(0);
        __syncthreads();
        if (s + 1 < NS) issue((s + 1) & 1, (s + 1) * 64);
        const uint32_t off = (s & 1) * ABUF;
#pragma unroll
        for (int kk = 0; kk < 4; kk++) {       // k16 steps
            uint32_t a[4][4], b[4][4];
#pragma unroll
            for (int t = 0; t < 4; t++)
                ldsm4(a[t][0], a[t][1], a[t][2], a[t][3], aBase + off + t * (16 * RSA) + kk * 32);
#pragma unroll
            for (int du = 0; du < 4; du++)
                ldsm4(b[du][0], b[du][1], b[du][2], b[du][3], bBase + off + du * (16 * RSA) + kk * 32);
#pragma unroll
            for (int t = 0; t < 4; t++)
#pragma unroll
                for (int du = 0; du < 4; du++) {
                    mma16(c[t][du * 2 + 0], a[t], b[du][0], b[du][1]);
                    mma16(c[t][du * 2 + 1], a[t], b[du][2], b[du][3]);
                }
        }
    }
}

// ===== core: C(128x128) = P(128x1024) * V(1024x128), V row-major [m][d], BK=64 ====
__device__ __forceinline__ void hgemm_pv(const __half* __restrict__ A,
                                         const __half* __restrict__ V,
                                         float c[4][8][4]) {
    extern __shared__ __align__(16) char smem_dyn[];
    char* sA = smem_dyn;
    char* sB = smem_dyn + 2 * ABUF;
    const int tid = threadIdx.x, lane = tid & 31, wid = tid >> 5;
    const int wm = (wid & 1) * 64, wn = (wid >> 1) * 64;
    const uint32_t sbA = smem_u32(sA), sbB = smem_u32(sB);
    const uint32_t aBase = sbA + (uint32_t)((wm + (lane & 7) + ((lane >> 3) & 1) * 8) * RSA
                                            + (lane >> 4) * 16);
    const uint32_t btBase = sbB + (uint32_t)(((lane & 7) + ((lane >> 3) & 1) * 8) * RSBT
                                             + (wn + (lane >> 4) * 8) * 2);

    auto issue = [&](int buf, int k0) {
        const uint32_t bA = sbA + buf * ABUF;
        const uint32_t bB = sbB + buf * BTBUF;
#pragma unroll
        for (int i = 0; i < 8; i++) {
            int ch = tid + i * 128;            // A: 128 rows x 8 chunks
            int r = ch >> 3, c16 = (ch & 7) * 16;
            cpa16(bA + r * RSA + c16, (const char*)(A + (size_t)r * 1024 + k0) + c16);
        }
#pragma unroll
        for (int i = 0; i < 8; i++) {          // B: 64 rows x 16 chunks
            int ch = tid + i * 128;
            int r = ch >> 4, c16 = (ch & 15) * 16;
            cpa16(bB + r * RSBT + c16, (const char*)(V + (size_t)(k0 + r) * HDq) + c16);
        }
        CP_COMMIT();
    };

    constexpr int NS = 1024 / 64;
    issue(0, 0);
#pragma unroll 1
    for (int s = 0; s < NS; s++) {
        CP_WAIT(0);
        __syncthreads();
        if (s + 1 < NS) issue((s + 1) & 1, (s + 1) * 64);
        const uint32_t offA = (s & 1) * ABUF;
        const uint32_t offB = (s & 1) * BTBUF;
#pragma unroll
        for (int kk = 0; kk < 4; kk++) {
            uint32_t a[4][4], b[4][4];
#pragma unroll
            for (int t = 0; t < 4; t++)
                ldsm4(a[t][0], a[t][1], a[t][2], a[t][3], aBase + offA + t * (16 * RSA) + kk * 32);
#pragma unroll
            for (int du = 0; du < 4; du++)
                ldsm4t(b[du][0], b[du][1], b[du][2], b[du][3],
                       btBase + offB + kk * (16 * RSBT) + du * 32);
#pragma unroll
            for (int t = 0; t < 4; t++)
#pragma unroll
                for (int du = 0; du < 4; du++) {
                    mma16(c[t][du * 2 + 0], a[t], b[du][0], b[du][1]);
                    mma16(c[t][du * 2 + 1], a[t], b[du][2], b[du][3]);
                }
        }
    }
}

// ---------------- kernels ----------------

__global__ void k_round16(const float* __restrict__ src, __half* __restrict__ dst, int n4) {
    int i = blockIdx.x * blockDim.x + threadIdx.x;
    if (i >= n4) return;
    float4 v = ((const float4*)src)[i];
    ((__half2*)dst)[2 * i]     = __floats2half2_rn(v.x, v.y);
    ((__half2*)dst)[2 * i + 1] = __floats2half2_rn(v.z, v.w);
}

// qkv = x @ w_qkv^T ; scatter fp16 into g_q/g_k/g_v [b,h,n,d]
__global__ void __launch_bounds__(128, 2) k_qkv() {
    const int row0 = blockIdx.y * 128;
    const int col0 = blockIdx.x * 128;
    float c[4][8][4] = {};
    hgemm_abt<Cq>(g_x + (size_t)row0 * Cq, Cq, g_wq + (size_t)col0 * Cq, Cq, c);

    const int part = col0 >> 9;
    const int h = (col0 & 511) >> 7;
    __half* dst = (part == 0) ? g_q : (part == 1) ? g_k : g_v;

    const int tid = threadIdx.x, lane = tid & 31, wid = tid >> 5;
    const int wm = (wid & 1) * 64, wn = (wid >> 1) * 64;
    const int lr = lane >> 2, lc = lane & 3;
#pragma unroll
    for (int t = 0; t < 4; t++)
#pragma unroll
        for (int u = 0; u < 8; u++) {
            const int d = wn + u * 8 + 2 * lc;
#pragma unroll
            for (int half = 0; half < 2; half++) {
                const int r = row0 + wm + t * 16 + lr + half * 8;
                const int b = r >> 10, n = r & 1023;
                __half* p = dst + ((size_t)((b * Hq + h) * Nq + n)) * HDq + d;
                *(__half2*)p = __floats2half2_rn(c[t][u][half * 2 + 0], c[t][u][half * 2 + 1]);
            }
        }
}

// S[z] = q[z] @ k[z]^T (raw f32; scale folded into mix)
__global__ void __launch_bounds__(128, 2) k_scores() {
    const int z = blockIdx.z;
    const int row0 = blockIdx.y * 128;
    const int col0 = blockIdx.x * 128;
    float c[4][8][4] = {};
    const __half* A = g_q + (size_t)z * Nq * HDq + (size_t)row0 * HDq;
    const __half* B = g_k + (size_t)z * Nq * HDq + (size_t)col0 * HDq;
    hgemm_abt<HDq>(A, HDq, B, HDq, c);

    float* S = g_s + (size_t)z * Nq * Nq;
    const int tid = threadIdx.x, lane = tid & 31, wid = tid >> 5;
    const int wm = (wid & 1) * 64, wn = (wid >> 1) * 64;
    const int lr = lane >> 2, lc = lane & 3;
#pragma unroll
    for (int t = 0; t < 4; t++)
#pragma unroll
        for (int u = 0; u < 8; u++) {
            const int col = col0 + wn + u * 8 + 2 * lc;
#pragma unroll
            for (int half = 0; half < 2; half++) {
                const int r = row0 + wm + t * 16 + lr + half * 8;
                *(float2*)(S + (size_t)r * Nq + col) =
                    make_float2(c[t][u][half * 2 + 0], c[t][u][half * 2 + 1]);
            }
        }
}

__device__ __forceinline__ float bred(float v, bool is_max, float* red) {
#pragma unroll
    for (int o = 16; o > 0; o >>= 1) {
        float t = __shfl_xor_sync(0xffffffffu, v, o);
        v = is_max ? fmaxf(v, t) : (v + t);
    }
    const int tid = threadIdx.x;
    if ((tid & 31) == 0) red[tid >> 5] = v;
    __syncthreads();
    if (tid == 0) {
        float r = red[0];
        for (int w = 1; w < 8; w++) r = is_max ? fmaxf(r, red[w]) : (r + red[w]);
        red[0] = r;
    }
    __syncthreads();
    float r = red[0];
    __syncthreads();
    return r;
}

// per (b,n): mix heads with M*SCALE, softmax; read f32 scores, write fp16 probs
__global__ void __launch_bounds__(256) k_mix_softmax(const float* __restrict__ w_main,
                                                     const float* __restrict__ w_rest) {
    __shared__ float red[8];
    const int bn = blockIdx.x;
    const int b = bn >> 10, n = bn & 1023;
    const int tid = threadIdx.x;
    const int m0 = tid * 4;
    const size_t base = ((size_t)(b * Hq) * Nq + n) * Nq;
    const size_t hstride = (size_t)Nq * Nq;

    float4 sh[Hq];
#pragma unroll
    for (int h = 0; h < Hq; h++)
        sh[h] = *(const float4*)(g_s + base + (size_t)h * hstride + m0);

    float Mr[Hq][Hq];
#pragma unroll
    for (int i = 0; i < Hq; i++)
#pragma unroll
        for (int j = 0; j < Hq; j++) {
            float w = (j == i) ? w_main[i] : w_rest[i * (Hq - 1) + j - (j > i ? 1 : 0)];
            Mr[i][j] = w * SCALEq;
        }

#pragma unroll
    for (int i = 0; i < Hq; i++) {
        float v[4];
        v[0] = Mr[i][0] * sh[0].x + Mr[i][1] * sh[1].x + Mr[i][2] * sh[2].x + Mr[i][3] * sh[3].x;
        v[1] = Mr[i][0] * sh[0].y + Mr[i][1] * sh[1].y + Mr[i][2] * sh[2].y + Mr[i][3] * sh[3].y;
        v[2] = Mr[i][0] * sh[0].z + Mr[i][1] * sh[1].z + Mr[i][2] * sh[2].z + Mr[i][3] * sh[3].z;
        v[3] = Mr[i][0] * sh[0].w + Mr[i][1] * sh[1].w + Mr[i][2] * sh[2].w + Mr[i][3] * sh[3].w;
        float lmax = fmaxf(fmaxf(v[0], v[1]), fmaxf(v[2], v[3]));
        const float gmax = bred(lmax, true, red);
        float lsum = 0.f;
#pragma unroll
        for (int t = 0; t < 4; t++) { v[t] = __expf(v[t] - gmax); lsum += v[t]; }
        const float gsum = bred(lsum, false, red);
        const float inv = 1.f / gsum;
        __half* p = g_p + base + (size_t)i * hstride + m0;
        *(__half2*)(p)     = __floats2half2_rn(v[0] * inv, v[1] * inv);
        *(__half2*)(p + 2) = __floats2half2_rn(v[2] * inv, v[3] * inv);
    }
}

// out[z] = P[z] @ V[z] -> g_y[b, n, h*HD + d] fp16
__global__ void __launch_bounds__(128, 2) k_pv() {
    const int z = blockIdx.z;
    const int row0 = blockIdx.y * 128;   // n
    float c[4][8][4] = {};
    const __half* A = g_p + (size_t)z * Nq * Nq + (size_t)row0 * Nq;
    const __half* V = g_v + (size_t)z * Nq * HDq;
    hgemm_pv(A, V, c);

    const int b = z >> 2, h = z & 3;
    const int tid = threadIdx.x, lane = tid & 31, wid = tid >> 5;
    const int wm = (wid & 1) * 64, wn = (wid >> 1) * 64;
    const int lr = lane >> 2, lc = lane & 3;
#pragma unroll
    for (int t = 0; t < 4; t++)
#pragma unroll
        for (int u = 0; u < 8; u++) {
            const int d = wn + u * 8 + 2 * lc;
#pragma unroll
            for (int half = 0; half < 2; half++) {
                const int n = row0 + wm + t * 16 + lr + half * 8;
                __half* p = g_y + ((size_t)b * Nq + n) * Cq + h * HDq + d;
                *(__half2*)p = __floats2half2_rn(c[t][u][half * 2 + 0], c[t][u][half * 2 + 1]);
            }
        }
}

// out = y @ w_proj^T + b_proj (f32 out)
__global__ void __launch_bounds__(128, 2)
k_proj(const float* __restrict__ bias, float* __restrict__ out) {
    const int row0 = blockIdx.y * 128;
    const int col0 = blockIdx.x * 128;
    float c[4][8][4] = {};
    hgemm_abt<Cq>(g_y + (size_t)row0 * Cq, Cq, g_wp + (size_t)col0 * Cq, Cq, c);

    const int tid = threadIdx.x, lane = tid & 31, wid = tid >> 5;
    const int wm = (wid & 1) * 64, wn = (wid >> 1) * 64;
    const int lr = lane >> 2, lc = lane & 3;
#pragma unroll
    for (int t = 0; t < 4; t++)
#pragma unroll
        for (int u = 0; u < 8; u++) {
            const int col = col0 + wn + u * 8 + 2 * lc;
            const float b0 = bias[col], b1 = bias[col + 1];
#pragma unroll
            for (int half = 0; half < 2; half++) {
                const int r = row0 + wm + t * 16 + lr + half * 8;
                *(float2*)(out + (size_t)r * Cq + col) =
                    make_float2(c[t][u][half * 2 + 0] + b0, c[t][u][half * 2 + 1] + b1);
            }
        }
}

// ---------------- launch ----------------
extern "C" void kernel_launch(void* const* d_in, const int* in_sizes, int n_in,
                              void* d_out, int out_size) {
    const float* x      = (const float*)d_in[0];
    const float* w_qkv  = (const float*)d_in[1];
    const float* w_proj = (const float*)d_in[2];
    const float* b_proj = (const float*)d_in[3];
    const float* w_main = (const float*)d_in[4];
    const float* w_rest = (const float*)d_in[5];
    float* out = (float*)d_out;

    __half* p_x;  cudaGetSymbolAddress((void**)&p_x,  g_x);
    __half* p_wq; cudaGetSymbolAddress((void**)&p_wq, g_wq);
    __half* p_wp; cudaGetSymbolAddress((void**)&p_wp, g_wp);

    const int dynSmem = 4 * ABUF;   // 73728 B (abt); pv uses less
    cudaFuncSetAttribute(k_qkv,    cudaFuncAttributeMaxDynamicSharedMemorySize, dynSmem);
    cudaFuncSetAttribute(k_scores, cudaFuncAttributeMaxDynamicSharedMemorySize, dynSmem);
    cudaFuncSetAttribute(k_pv,     cudaFuncAttributeMaxDynamicSharedMemorySize, dynSmem);
    cudaFuncSetAttribute(k_proj,   cudaFuncAttributeMaxDynamicSharedMemorySize, dynSmem);

    {
        int n4 = Bq * Nq * Cq / 4;
        k_round16<<<(n4 + 255) / 256, 256>>>(x, p_x, n4);
        n4 = 3 * Cq * Cq / 4;
        k_round16<<<(n4 + 255) / 256, 256>>>(w_qkv, p_wq, n4);
        n4 = Cq * Cq / 4;
        k_round16<<<(n4 + 255) / 256, 256>>>(w_proj, p_wp, n4);
    }
    k_qkv<<<dim3(1536 / 128, (Bq * Nq) / 128), 128, dynSmem>>>();
    k_scores<<<dim3(Nq / 128, Nq / 128, Bq * Hq), 128, dynSmem>>>();
    k_mix_softmax<<<Bq * Nq, 256>>>(w_main, w_rest);
    k_pv<<<dim3(1, Nq / 128, Bq * Hq), 128, dynSmem>>>();
    k_proj<<<dim3(Cq / 128, (Bq * Nq) / 128), 128, dynSmem>>>(b_proj, out);
}

// round 16
// speedup vs baseline: 1.9533x; 1.0222x over previous
#include <cuda_runtime.h>
#include <cuda_fp16.h>
#include <math.h>
#include <stdint.h>

#define Bq 8
#define Nq 1024
#define Cq 512
#define Hq 4
#define HDq 128
#define SCALEq 0.08838834764831845f

// ---------------- scratch ----------------
__device__ __half g_q[Bq * Hq * Nq * HDq];
__device__ __half g_k[Bq * Hq * Nq * HDq];
__device__ __half g_v[Bq * Hq * Nq * HDq];
__device__ float  g_s[(size_t)Bq * Hq * Nq * Nq];   // raw scores f32
__device__ __half g_y[Bq * Nq * Cq];
__device__ __half g_x[Bq * Nq * Cq];
__device__ __half g_wq[3 * Cq * Cq];
__device__ __half g_wp[Cq * Cq];

// ---------------- helpers ----------------
__device__ __forceinline__ uint32_t smem_u32(const void* p) {
    uint32_t a;
    asm("{ .reg .u64 t; cvta.to.shared.u64 t, %1; cvt.u32.u64 %0, t; }" : "=r"(a) : "l"(p));
    return a;
}
__device__ __forceinline__ void cpa16(uint32_t dst, const void* src) {
    asm volatile("cp.async.ca.shared.global [%0], [%1], 16;" :: "r"(dst), "l"(src));
}
#define CP_COMMIT() asm volatile("cp.async.commit_group;")
#define CP_WAIT(n)  asm volatile("cp.async.wait_group %0;" :: "n"(n))

__device__ __forceinline__ void ldsm4(uint32_t& r0, uint32_t& r1, uint32_t& r2, uint32_t& r3,
                                      uint32_t addr) {
    asm volatile("ldmatrix.sync.aligned.m8n8.x4.shared.b16 {%0,%1,%2,%3}, [%4];"
                 : "=r"(r0), "=r"(r1), "=r"(r2), "=r"(r3) : "r"(addr));
}
__device__ __forceinline__ void ldsm4t(uint32_t& r0, uint32_t& r1, uint32_t& r2, uint32_t& r3,
                                       uint32_t addr) {
    asm volatile("ldmatrix.sync.aligned.m8n8.x4.trans.shared.b16 {%0,%1,%2,%3}, [%4];"
                 : "=r"(r0), "=r"(r1), "=r"(r2), "=r"(r3) : "r"(addr));
}
__device__ __forceinline__ void mma16(float c[4], const uint32_t a[4], uint32_t b0, uint32_t b1) {
    asm volatile(
        "mma.sync.aligned.m16n8k16.row.col.f32.f16.f16.f32 "
        "{%0,%1,%2,%3},{%4,%5,%6,%7},{%8,%9},{%0,%1,%2,%3};"
        : "+f"(c[0]), "+f"(c[1]), "+f"(c[2]), "+f"(c[3])
        : "r"(a[0]), "r"(a[1]), "r"(a[2]), "r"(a[3]), "r"(b0), "r"(b1));
}

// BK=64 GEMM cores. A/B abt smem row: 64 halfs + 8 pad = 144 B.
#define RSA 144
#define ABUF 18432   // 128*144

// ===== core: C(128x128) = A(128xK) * B(128xK)^T, fp16 K-major, 128 thr, BK=64 =====
template <int K>
__device__ __forceinline__ void hgemm_abt(const __half* __restrict__ A, int lda,
                                          const __half* __restrict__ B, int ldb,
                                          float c[4][8][4]) {
    extern __shared__ __align__(16) char smem_dyn[];
    char* sA = smem_dyn;
    char* sB = smem_dyn + 2 * ABUF;
    const int tid = threadIdx.x, lane = tid & 31, wid = tid >> 5;
    const int wm = (wid & 1) * 64, wn = (wid >> 1) * 64;
    const uint32_t sbA = smem_u32(sA), sbB = smem_u32(sB);
    const uint32_t aBase = sbA + (uint32_t)((wm + (lane & 7) + ((lane >> 3) & 1) * 8) * RSA
                                            + (lane >> 4) * 16);
    const uint32_t bBase = sbB + (uint32_t)((wn + (lane & 7) + (lane >> 4) * 8) * RSA
                                            + ((lane >> 3) & 1) * 16);

    auto issue = [&](int buf, int k0) {
        const uint32_t bA = sbA + buf * ABUF;
        const uint32_t bB = sbB + buf * ABUF;
#pragma unroll
        for (int i = 0; i < 8; i++) {
            int ch = tid + i * 128;
            int r = ch >> 3, c16 = (ch & 7) * 16;
            cpa16(bA + r * RSA + c16, (const char*)(A + (size_t)r * lda + k0) + c16);
            cpa16(bB + r * RSA + c16, (const char*)(B + (size_t)r * ldb + k0) + c16);
        }
        CP_COMMIT();
    };

    constexpr int NS = K / 64;
    issue(0, 0);
#pragma unroll 1
    for (int s = 0; s < NS; s++) {
        CP_WAIT(0);
        __syncthreads();
        if (s + 1 < NS) issue((s + 1) & 1, (s + 1) * 64);
        const uint32_t off = (s & 1) * ABUF;
#pragma unroll
        for (int kk = 0; kk < 4; kk++) {
            uint32_t a[4][4], b[4][4];
#pragma unroll
            for (int t = 0; t < 4; t++)
                ldsm4(a[t][0], a[t][1], a[t][2], a[t][3], aBase + off + t * (16 * RSA) + kk * 32);
#pragma unroll
            for (int du = 0; du < 4; du++)
                ldsm4(b[du][0], b[du][1], b[du][2], b[du][3], bBase + off + du * (16 * RSA) + kk * 32);
#pragma unroll
            for (int t = 0; t < 4; t++)
#pragma unroll
                for (int du = 0; du < 4; du++) {
                    mma16(c[t][du * 2 + 0], a[t], b[du][0], b[du][1]);
                    mma16(c[t][du * 2 + 1], a[t], b[du][2], b[du][3]);
                }
        }
    }
}

// ---------------- kernels ----------------

__global__ void k_round16(const float* __restrict__ src, __half* __restrict__ dst, int n4) {
    int i = blockIdx.x * blockDim.x + threadIdx.x;
    if (i >= n4) return;
    float4 v = ((const float4*)src)[i];
    ((__half2*)dst)[2 * i]     = __floats2half2_rn(v.x, v.y);
    ((__half2*)dst)[2 * i + 1] = __floats2half2_rn(v.z, v.w);
}

// qkv = x @ w_qkv^T ; scatter fp16 into g_q/g_k/g_v [b,h,n,d]
__global__ void __launch_bounds__(128, 2) k_qkv() {
    const int row0 = blockIdx.y * 128;
    const int col0 = blockIdx.x * 128;
    float c[4][8][4] = {};
    hgemm_abt<Cq>(g_x + (size_t)row0 * Cq, Cq, g_wq + (size_t)col0 * Cq, Cq, c);

    const int part = col0 >> 9;
    const int h = (col0 & 511) >> 7;
    __half* dst = (part == 0) ? g_q : (part == 1) ? g_k : g_v;

    const int tid = threadIdx.x, lane = tid & 31, wid = tid >> 5;
    const int wm = (wid & 1) * 64, wn = (wid >> 1) * 64;
    const int lr = lane >> 2, lc = lane & 3;
#pragma unroll
    for (int t = 0; t < 4; t++)
#pragma unroll
        for (int u = 0; u < 8; u++) {
            const int d = wn + u * 8 + 2 * lc;
#pragma unroll
            for (int half = 0; half < 2; half++) {
                const int r = row0 + wm + t * 16 + lr + half * 8;
                const int b = r >> 10, n = r & 1023;
                __half* p = dst + ((size_t)((b * Hq + h) * Nq + n)) * HDq + d;
                *(__half2*)p = __floats2half2_rn(c[t][u][half * 2 + 0], c[t][u][half * 2 + 1]);
            }
        }
}

// S[z] = q[z] @ k[z]^T (raw f32; scale folded into mix)
__global__ void __launch_bounds__(128, 2) k_scores() {
    const int z = blockIdx.z;
    const int row0 = blockIdx.y * 128;
    const int col0 = blockIdx.x * 128;
    float c[4][8][4] = {};
    const __half* A = g_q + (size_t)z * Nq * HDq + (size_t)row0 * HDq;
    const __half* B = g_k + (size_t)z * Nq * HDq + (size_t)col0 * HDq;
    hgemm_abt<HDq>(A, HDq, B, HDq, c);

    float* S = g_s + (size_t)z * Nq * Nq;
    const int tid = threadIdx.x, lane = tid & 31, wid = tid >> 5;
    const int wm = (wid & 1) * 64, wn = (wid >> 1) * 64;
    const int lr = lane >> 2, lc = lane & 3;
#pragma unroll
    for (int t = 0; t < 4; t++)
#pragma unroll
        for (int u = 0; u < 8; u++) {
            const int col = col0 + wn + u * 8 + 2 * lc;
#pragma unroll
            for (int half = 0; half < 2; half++) {
                const int r = row0 + wm + t * 16 + lr + half * 8;
                *(float2*)(S + (size_t)r * Nq + col) =
                    make_float2(c[t][u][half * 2 + 0], c[t][u][half * 2 + 1]);
            }
        }
}

// ================= fused mix + online-softmax + PV =================
// CTA: (b, 64-query block), all 4 heads. 256 threads = 8 warps;
// warp pair (wid>>1)=head i; warp (wid&1) owns d-half. Loop 32-key blocks.
// Smem layout (bytes) — ALL row strides multiples of 16 (ldsm requirement):
#define MSP_S_OFF   0            // [2][4][64][144]  S tiles f32
#define MSP_S_BUF   36864
#define MSP_S_H     9216
#define MSP_V_OFF   73728        // [2][4][32][272]  V tiles fp16
#define MSP_V_BUF   34816
#define MSP_V_H     8704
#define MSP_P_OFF   143360       // [4][64][80]      probs fp16 (32 h + 8 pad = 80 B row)
#define MSP_P_H     5120
#define MSP_M_OFF   163840       // [4][64] f32 running max
#define MSP_L_OFF   164864       // [4][64] f32 running sum
#define MSP_R_OFF   165888       // [4][64] f32 row scale this stage
#define MSP_SMEM    166912

__global__ void __launch_bounds__(256, 1)
k_msp(const float* __restrict__ w_main, const float* __restrict__ w_rest) {
    extern __shared__ __align__(16) char sm[];
    const int tid = threadIdx.x, lane = tid & 31, wid = tid >> 5;
    const int b = blockIdx.y;
    const int n0 = blockIdx.x * 64;
    const int i = wid >> 1;               // head of this warp pair
    const int dhalf = (wid & 1) * 64;     // d range of this warp
    const int lane_g = (wid & 1) * 32 + lane;  // 0..63 within pair
    const uint32_t sb = smem_u32(sm);

    float* sm_m = (float*)(sm + MSP_M_OFF);
    float* sm_l = (float*)(sm + MSP_L_OFF);
    float* sm_r = (float*)(sm + MSP_R_OFF);

    // mix row for this head (scale folded)
    float Mi[Hq];
#pragma unroll
    for (int j = 0; j < Hq; j++)
        Mi[j] = ((j == i) ? w_main[i] : w_rest[i * (Hq - 1) + j - (j > i ? 1 : 0)]) * SCALEq;

    sm_m[tid] = -INFINITY;
    sm_l[tid] = 0.f;

    // cp.async issue for stage s into buf
    auto issue = [&](int buf, int m0) {
        const uint32_t bS = sb + MSP_S_OFF + buf * MSP_S_BUF;
        const uint32_t bV = sb + MSP_V_OFF + buf * MSP_V_BUF;
#pragma unroll
        for (int k = 0; k < 8; k++) {                 // S: 2048 chunks
            int ch = tid + k * 256;
            int h = ch >> 9, r = (ch >> 3) & 63, c16 = (ch & 7) * 16;
            const char* src = (const char*)g_s
                + ((((size_t)(b * Hq + h) * Nq + n0 + r) * Nq + m0) << 2) + c16;
            cpa16(bS + h * MSP_S_H + r * 144 + c16, src);
        }
#pragma unroll
        for (int k = 0; k < 8; k++) {                 // V: 2048 chunks
            int ch = tid + k * 256;
            int h = ch >> 9, r = (ch >> 4) & 31, c16 = (ch & 15) * 16;
            const char* src = (const char*)g_v
                + ((((size_t)(b * Hq + h) * Nq + m0 + r) * HDq) << 1) + c16;
            cpa16(bV + h * MSP_V_H + r * 272 + c16, src);
        }
        CP_COMMIT();
    };

    // ldsm bases (P row stride 80 B = 16*5 -> ldsm-legal)
    const uint32_t aBase = sb + MSP_P_OFF + i * MSP_P_H
        + (uint32_t)(((lane & 7) + ((lane >> 3) & 1) * 8) * 80 + (lane >> 4) * 16);
    const uint32_t btBase0 = sb + MSP_V_OFF + i * MSP_V_H
        + (uint32_t)(((lane & 7) + ((lane >> 3) & 1) * 8) * 272
                     + (dhalf + (lane >> 4) * 8) * 2);

    float c[4][8][4] = {};

    issue(0, 0);
    __syncthreads();   // also covers sm_m/sm_l init

#pragma unroll 1
    for (int s = 0; s < 32; s++) {
        CP_WAIT(0);
        __syncthreads();
        if (s + 1 < 32) issue((s + 1) & 1, (s + 1) * 32);

        // ---- probs phase: lane owns row n = lane_g of head i ----
        {
            const int n = lane_g;
            float L[32];
#pragma unroll
            for (int m = 0; m < 32; m++) L[m] = 0.f;
#pragma unroll
            for (int h = 0; h < Hq; h++) {
                const float4* sp = (const float4*)(sm + MSP_S_OFF + (s & 1) * MSP_S_BUF
                                                   + h * MSP_S_H + n * 144);
                const float mh = Mi[h];
#pragma unroll
                for (int q = 0; q < 8; q++) {
                    float4 v = sp[q];
                    L[4 * q + 0] += mh * v.x;
                    L[4 * q + 1] += mh * v.y;
                    L[4 * q + 2] += mh * v.z;
                    L[4 * q + 3] += mh * v.w;
                }
            }
            float bm = L[0];
#pragma unroll
            for (int m = 1; m < 32; m++) bm = fmaxf(bm, L[m]);
            const float m_old = sm_m[i * 64 + n];
            const float m_new = fmaxf(m_old, bm);
            const float scale = __expf(m_old - m_new);
            float psum = 0.f;
            __half2* pp = (__half2*)(sm + MSP_P_OFF + i * MSP_P_H + n * 80);
#pragma unroll
            for (int m = 0; m < 16; m++) {
                float p0 = __expf(L[2 * m + 0] - m_new);
                float p1 = __expf(L[2 * m + 1] - m_new);
                psum += p0 + p1;
                pp[m] = __floats2half2_rn(p0, p1);
            }
            sm_m[i * 64 + n] = m_new;
            sm_l[i * 64 + n] = sm_l[i * 64 + n] * scale + psum;
            sm_r[i * 64 + n] = scale;
        }
        __syncthreads();

        // ---- MMA phase: rescale O, then O += P_i * V_i ----
        {
            const int lr = lane >> 2;
#pragma unroll
            for (int t = 0; t < 4; t++)
#pragma unroll
                for (int half = 0; half < 2; half++) {
                    const float sc = sm_r[i * 64 + t * 16 + lr + half * 8];
#pragma unroll
                    for (int u = 0; u < 8; u++) {
                        c[t][u][half * 2 + 0] *= sc;
                        c[t][u][half * 2 + 1] *= sc;
                    }
                }
            const uint32_t btBase = btBase0 + (s & 1) * MSP_V_BUF;
#pragma unroll
            for (int kk = 0; kk < 2; kk++) {
                uint32_t a[4][4], bfr[4][4];
#pragma unroll
                for (int t = 0; t < 4; t++)
                    ldsm4(a[t][0], a[t][1], a[t][2], a[t][3], aBase + t * (16 * 80) + kk * 32);
#pragma unroll
                for (int du = 0; du < 4; du++)
                    ldsm4t(bfr[du][0], bfr[du][1], bfr[du][2], bfr[du][3],
                           btBase + kk * (16 * 272) + du * 32);
#pragma unroll
                for (int t = 0; t < 4; t++)
#pragma unroll
                    for (int du = 0; du < 4; du++) {
                        mma16(c[t][du * 2 + 0], a[t], bfr[du][0], bfr[du][1]);
                        mma16(c[t][du * 2 + 1], a[t], bfr[du][2], bfr[du][3]);
                    }
            }
        }
        __syncthreads();
    }

    // ---- epilogue: O /= l, write fp16 to g_y[b, n, i*128 + d] ----
    {
        const int lr = lane >> 2, lc = lane & 3;
#pragma unroll
        for (int t = 0; t < 4; t++)
#pragma unroll
            for (int half = 0; half < 2; half++) {
                const int row = t * 16 + lr + half * 8;
                const float inv = 1.f / sm_l[i * 64 + row];
                const int n = n0 + row;
#pragma unroll
                for (int u = 0; u < 8; u++) {
                    const int d = dhalf + u * 8 + 2 * lc;
                    __half* p = g_y + ((size_t)b * Nq + n) * Cq + i * HDq + d;
                    *(__half2*)p = __floats2half2_rn(c[t][u][half * 2 + 0] * inv,
                                                     c[t][u][half * 2 + 1] * inv);
                }
            }
    }
}

// out = y @ w_proj^T + b_proj (f32 out)
__global__ void __launch_bounds__(128, 2)
k_proj(const float* __restrict__ bias, float* __restrict__ out) {
    const int row0 = blockIdx.y * 128;
    const int col0 = blockIdx.x * 128;
    float c[4][8][4] = {};
    hgemm_abt<Cq>(g_y + (size_t)row0 * Cq, Cq, g_wp + (size_t)col0 * Cq, Cq, c);

    const int tid = threadIdx.x, lane = tid & 31, wid = tid >> 5;
    const int wm = (wid & 1) * 64, wn = (wid >> 1) * 64;
    const int lr = lane >> 2, lc = lane & 3;
#pragma unroll
    for (int t = 0; t < 4; t++)
#pragma unroll
        for (int u = 0; u < 8; u++) {
            const int col = col0 + wn + u * 8 + 2 * lc;
            const float b0 = bias[col], b1 = bias[col + 1];
#pragma unroll
            for (int half = 0; half < 2; half++) {
                const int r = row0 + wm + t * 16 + lr + half * 8;
                *(float2*)(out + (size_t)r * Cq + col) =
                    make_float2(c[t][u][half * 2 + 0] + b0, c[t][u][half * 2 + 1] + b1);
            }
        }
}

// ---------------- launch ----------------
extern "C" void kernel_launch(void* const* d_in, const int* in_sizes, int n_in,
                              void* d_out, int out_size) {
    const float* x      = (const float*)d_in[0];
    const float* w_qkv  = (const float*)d_in[1];
    const float* w_proj = (const float*)d_in[2];
    const float* b_proj = (const float*)d_in[3];
    const float* w_main = (const float*)d_in[4];
    const float* w_rest = (const float*)d_in[5];
    float* out = (float*)d_out;

    __half* p_x;  cudaGetSymbolAddress((void**)&p_x,  g_x);
    __half* p_wq; cudaGetSymbolAddress((void**)&p_wq, g_wq);
    __half* p_wp; cudaGetSymbolAddress((void**)&p_wp, g_wp);

    const int dynSmem = 4 * ABUF;   // 73728 B for abt cores
    cudaFuncSetAttribute(k_qkv,    cudaFuncAttributeMaxDynamicSharedMemorySize, dynSmem);
    cudaFuncSetAttribute(k_scores, cudaFuncAttributeMaxDynamicSharedMemorySize, dynSmem);
    cudaFuncSetAttribute(k_proj,   cudaFuncAttributeMaxDynamicSharedMemorySize, dynSmem);
    cudaFuncSetAttribute(k_msp,    cudaFuncAttributeMaxDynamicSharedMemorySize, MSP_SMEM);

    {
        int n4 = Bq * Nq * Cq / 4;
        k_round16<<<(n4 + 255) / 256, 256>>>(x, p_x, n4);
        n4 = 3 * Cq * Cq / 4;
        k_round16<<<(n4 + 255) / 256, 256>>>(w_qkv, p_wq, n4);
        n4 = Cq * Cq / 4;
        k_round16<<<(n4 + 255) / 256, 256>>>(w_proj, p_wp, n4);
    }
    k_qkv<<<dim3(1536 / 128, (Bq * Nq) / 128), 128, dynSmem>>>();
    k_scores<<<dim3(Nq / 128, Nq / 128, Bq * Hq), 128, dynSmem>>>();
    k_msp<<<dim3(Nq / 64, Bq), 256, MSP_SMEM>>>(w_main, w_rest);
    k_proj<<<dim3(Cq / 128, (Bq * Nq) / 128), 128, dynSmem>>>(b_proj, out);
}